// round 3
// baseline (speedup 1.0000x reference)
#include <cuda_runtime.h>
#include <cstdint>

// Problem constants (fixed by the dataset)
#define NN     10000        // nodes
#define LD     13           // volume side
#define VOL    2197         // 13^3
#define KNB    8            // neighbors
#define PD     19           // padded side (13 + 2*3)
#define PVOL   6859         // 19^3
#define BUFB   6137         // 19*19*17 (largest ping-pong partner)

static __device__ float g_s1[(size_t)NN * VOL];  // smoothed stage 1
static __device__ float g_s2[(size_t)NN * VOL];  // smoothed stage 2

// One separable 3-tap pooling pass. Output dims (OA,OB,OC), input addressed as
// i*S0 + j*S1 + k, taps at +0,+RS,+2*RS. All template params are literals so
// the % / / fold to mul-shift.
template<int OA, int OB, int OC, int S0, int S1, int RS, bool ISMAX>
__device__ __forceinline__ void pool_pass(const float* __restrict__ in,
                                          float* __restrict__ out, float scale) {
    constexpr int TOT = OA * OB * OC;
    for (int o = threadIdx.x; o < TOT; o += blockDim.x) {
        int k = o % OC;
        int t = o / OC;
        int j = t % OB;
        int i = t / OB;
        const float* p = in + i * S0 + j * S1 + k;
        float v0 = p[0], v1 = p[RS], v2 = p[2 * RS];
        out[o] = ISMAX ? fmaxf(v0, fmaxf(v1, v2)) : (v0 + v1 + v2) * scale;
    }
    __syncthreads();
}

// Edge-pad a 13^3 volume (in C) into a 19^3 volume (A) with clamp-replicate.
__device__ __forceinline__ void pad_edge(const float* __restrict__ C,
                                         float* __restrict__ A) {
    for (int p = threadIdx.x; p < PVOL; p += blockDim.x) {
        int z = p % PD;
        int t = p / PD;
        int y = t % PD;
        int x = t / PD;
        int sx = min(max(x - 3, 0), LD - 1);
        int sy = min(max(y - 3, 0), LD - 1);
        int sz = min(max(z - 3, 0), LD - 1);
        A[p] = C[(sx * LD + sy) * LD + sz];
    }
    __syncthreads();
}

// smooth = maxpool3 -> avgpool3 -> avgpool3, all separable. Input: padded 19^3
// in A. Result: 13^3 in B[0..2196].
__device__ __forceinline__ void smooth_smem(float* A, float* B) {
    pool_pass<19, 19, 17, 361, 19,   1, true >(A, B, 1.0f);  // max z: 19,19,19 -> 19,19,17
    pool_pass<19, 17, 17, 323, 17,  17, true >(B, A, 1.0f);  // max y: -> 19,17,17
    pool_pass<17, 17, 17, 289, 17, 289, true >(A, B, 1.0f);  // max x: -> 17^3
    pool_pass<17, 17, 15, 289, 17,   1, false>(B, A, 1.0f);  // avg z: -> 17,17,15
    pool_pass<17, 15, 15, 255, 15,  15, false>(A, B, 1.0f);  // avg y: -> 17,15,15
    pool_pass<15, 15, 15, 225, 15, 225, false>(B, A, 1.0f / 27.0f); // avg x -> 15^3
    pool_pass<15, 15, 13, 225, 15,   1, false>(A, B, 1.0f);  // avg z: -> 15,15,13
    pool_pass<15, 13, 13, 195, 13,  13, false>(B, A, 1.0f);  // avg y: -> 15,13,13
    pool_pass<13, 13, 13, 169, 13, 169, false>(A, B, 1.0f / 27.0f); // avg x -> 13^3
}

// Kernel 1: s1[n] = smooth(alpha1 + alpha0 * cost[n])
__global__ void __launch_bounds__(256)
k_stage1(const float* __restrict__ cost, const float* __restrict__ alpha) {
    extern __shared__ float sm[];
    float* A = sm;           // PVOL floats
    float* B = sm + PVOL;    // BUFB floats (also used as 13^3 staging)
    int n = blockIdx.x;
    float a0 = alpha[0], a1 = alpha[1];
    const float* src = cost + (size_t)n * VOL;
    for (int v = threadIdx.x; v < VOL; v += blockDim.x)
        B[v] = a1 + a0 * src[v];
    __syncthreads();
    pad_edge(B, A);
    smooth_smem(A, B);
    float* dst = g_s1 + (size_t)n * VOL;
    for (int v = threadIdx.x; v < VOL; v += blockDim.x)
        dst[v] = B[v];
}

// Kernel 2: gather s1 over knn -> combine with original cost -> smooth -> s2
__global__ void __launch_bounds__(256)
k_stage2(const float* __restrict__ cost, const int* __restrict__ knn,
         const float* __restrict__ dist, const float* __restrict__ alpha) {
    extern __shared__ float sm[];
    float* A = sm;
    float* B = sm + PVOL;
    __shared__ float ws[KNB];
    __shared__ int   nb[KNB];
    int n = blockIdx.x;
    if (threadIdx.x < KNB) {
        ws[threadIdx.x] = __expf(-dist[n * KNB + threadIdx.x] * 0.005f); // 1/(2*10^2)
        nb[threadIdx.x] = knn[n * KNB + threadIdx.x];
    }
    __syncthreads();
    float w0 = ws[0], w1 = ws[1], w2 = ws[2], w3 = ws[3];
    float w4 = ws[4], w5 = ws[5], w6 = ws[6], w7 = ws[7];
    float inv_norm = 1.0f / (w0 + w1 + w2 + w3 + w4 + w5 + w6 + w7);
    const float* p0 = g_s1 + (size_t)nb[0] * VOL;
    const float* p1 = g_s1 + (size_t)nb[1] * VOL;
    const float* p2 = g_s1 + (size_t)nb[2] * VOL;
    const float* p3 = g_s1 + (size_t)nb[3] * VOL;
    const float* p4 = g_s1 + (size_t)nb[4] * VOL;
    const float* p5 = g_s1 + (size_t)nb[5] * VOL;
    const float* p6 = g_s1 + (size_t)nb[6] * VOL;
    const float* p7 = g_s1 + (size_t)nb[7] * VOL;
    float a0 = alpha[0], a1 = alpha[1], a2 = alpha[2], a3 = alpha[3], a4 = alpha[4];
    const float* src = cost + (size_t)n * VOL;
    for (int v = threadIdx.x; v < VOL; v += blockDim.x) {
        float g = w0 * p0[v] + w1 * p1[v] + w2 * p2[v] + w3 * p3[v]
                + w4 * p4[v] + w5 * p5[v] + w6 * p6[v] + w7 * p7[v];
        B[v] = a4 + a2 * (a1 + a0 * src[v]) + a3 * g * inv_norm;
    }
    __syncthreads();
    pad_edge(B, A);
    smooth_smem(A, B);
    float* dst = g_s2 + (size_t)n * VOL;
    for (int v = threadIdx.x; v < VOL; v += blockDim.x)
        dst[v] = B[v];
}

// Kernel 3: out[n] = alpha5 * (gather s2 over knn) / norm
__global__ void __launch_bounds__(256)
k_stage3(const int* __restrict__ knn, const float* __restrict__ dist,
         const float* __restrict__ alpha, float* __restrict__ out) {
    __shared__ float ws[KNB];
    __shared__ int   nb[KNB];
    int n = blockIdx.x;
    if (threadIdx.x < KNB) {
        ws[threadIdx.x] = __expf(-dist[n * KNB + threadIdx.x] * 0.005f);
        nb[threadIdx.x] = knn[n * KNB + threadIdx.x];
    }
    __syncthreads();
    float w0 = ws[0], w1 = ws[1], w2 = ws[2], w3 = ws[3];
    float w4 = ws[4], w5 = ws[5], w6 = ws[6], w7 = ws[7];
    float inv_norm = 1.0f / (w0 + w1 + w2 + w3 + w4 + w5 + w6 + w7);
    float a5 = alpha[5];
    float s = a5 * inv_norm;
    const float* p0 = g_s2 + (size_t)nb[0] * VOL;
    const float* p1 = g_s2 + (size_t)nb[1] * VOL;
    const float* p2 = g_s2 + (size_t)nb[2] * VOL;
    const float* p3 = g_s2 + (size_t)nb[3] * VOL;
    const float* p4 = g_s2 + (size_t)nb[4] * VOL;
    const float* p5 = g_s2 + (size_t)nb[5] * VOL;
    const float* p6 = g_s2 + (size_t)nb[6] * VOL;
    const float* p7 = g_s2 + (size_t)nb[7] * VOL;
    float* dst = out + (size_t)n * VOL;
    for (int v = threadIdx.x; v < VOL; v += blockDim.x) {
        float g = w0 * p0[v] + w1 * p1[v] + w2 * p2[v] + w3 * p3[v]
                + w4 * p4[v] + w5 * p5[v] + w6 * p6[v] + w7 * p7[v];
        dst[v] = s * g;
    }
}

extern "C" void kernel_launch(void* const* d_in, const int* in_sizes, int n_in,
                              void* d_out, int out_size) {
    const float* cost  = (const float*)d_in[0];
    const int*   knn   = (const int*)d_in[1];
    const float* dist  = (const float*)d_in[2];
    const float* alpha = (const float*)d_in[3];
    float* out = (float*)d_out;

    const int smem = (PVOL + BUFB) * (int)sizeof(float);  // 51984 B
    cudaFuncSetAttribute(k_stage1, cudaFuncAttributeMaxDynamicSharedMemorySize, smem);
    cudaFuncSetAttribute(k_stage2, cudaFuncAttributeMaxDynamicSharedMemorySize, smem);

    k_stage1<<<NN, 256, smem>>>(cost, alpha);
    k_stage2<<<NN, 256, smem>>>(cost, knn, dist, alpha);
    k_stage3<<<NN, 256>>>(knn, dist, alpha, out);
}

// round 4
// speedup vs baseline: 2.0680x; 2.0680x over previous
#include <cuda_runtime.h>
#include <cstdint>

// Problem constants (fixed by the dataset)
#define NN     10000        // nodes
#define LD     13           // volume side
#define VOL    2197         // 13^3
#define KNB    8            // neighbors
#define PD     19           // padded side (13 + 2*3)
#define PVOL   6859         // 19^3
#define BUFB   6137         // 19*19*17 (largest B-side intermediate)

static __device__ float g_s1[(size_t)NN * VOL];  // smoothed stage 1
static __device__ float g_s2[(size_t)NN * VOL];  // smoothed stage 2

// Line-oriented separable 3-tap pooling pass, sliding window along the tap
// axis. Each thread owns whole lines: ONE div/mod per line, ONE smem load per
// input element (vs 3 per output in the naive form).
//   NL    : number of lines
//   BD    : line -> (a,b) split divisor (b = line % BD, a = line / BD)
//   IA,IB : input strides for a,b
//   OAs,OBs: output strides for a,b
//   LOOP  : outputs per line (output extent along tap axis)
//   ISTEP : input stride along tap axis
//   OSTEP : output stride along tap axis
template<int NL, int BD, int IA, int IB, int OAs, int OBs,
         int LOOP, int ISTEP, int OSTEP, bool ISMAX>
__device__ __forceinline__ void pool_line(const float* __restrict__ in,
                                          float* __restrict__ out, float scale) {
    for (int line = threadIdx.x; line < NL; line += blockDim.x) {
        int b = line % BD;
        int a = line / BD;
        const float* p = in + a * IA + b * IB;
        float* q = out + a * OAs + b * OBs;
        float v0 = p[0];
        float v1 = p[ISTEP];
        #pragma unroll
        for (int t = 0; t < LOOP; ++t) {
            float v2 = p[(t + 2) * ISTEP];
            q[t * OSTEP] = ISMAX ? fmaxf(v0, fmaxf(v1, v2))
                                 : (v0 + v1 + v2) * scale;
            v0 = v1; v1 = v2;
        }
    }
    __syncthreads();
}

// Edge-pad 13^3 (in C) -> 19^3 (in A), clamp-replicate. Line-oriented:
// load the 13 source values once, store 19 with compile-time clamped indices.
__device__ __forceinline__ void pad_edge(const float* __restrict__ C,
                                         float* __restrict__ A) {
    for (int line = threadIdx.x; line < PD * PD; line += blockDim.x) {
        int y = line % PD;
        int x = line / PD;
        int sx = min(max(x - 3, 0), LD - 1);
        int sy = min(max(y - 3, 0), LD - 1);
        const float* src = C + (sx * LD + sy) * LD;
        float* dst = A + line * PD;
        float s[LD];
        #pragma unroll
        for (int z = 0; z < LD; ++z) s[z] = src[z];
        #pragma unroll
        for (int z = 0; z < PD; ++z) {
            constexpr int dummy = 0; (void)dummy;
            int sz = (z < 3) ? 0 : ((z > 15) ? 12 : (z - 3));
            dst[z] = s[sz];
        }
    }
    __syncthreads();
}

// smooth = maxpool3 -> avgpool3 -> avgpool3, separable, line-sliding.
// Input: padded 19^3 in A. Result: 13^3 in B[0..2196].
__device__ __forceinline__ void smooth_smem(float* A, float* B) {
    // max z: (19,19,19)->(19,19,17)
    pool_line<361, 19, 361, 19, 323, 17, 17,   1,   1, true >(A, B, 1.0f);
    // max y: ->(19,17,17)   lines (i,k)
    pool_line<323, 17, 323,  1, 289,  1, 17,  17,  17, true >(B, A, 1.0f);
    // max x: ->(17,17,17)   lines (j,k)
    pool_line<289, 17,  17,  1,  17,  1, 17, 289, 289, true >(A, B, 1.0f);
    // avg z: ->(17,17,15)
    pool_line<289, 17, 289, 17, 255, 15, 15,   1,   1, false>(B, A, 1.0f);
    // avg y: ->(17,15,15)   lines (i,k)
    pool_line<255, 15, 255,  1, 225,  1, 15,  15,  15, false>(A, B, 1.0f);
    // avg x: ->(15,15,15)   lines (j,k)
    pool_line<225, 15,  15,  1,  15,  1, 15, 225, 225, false>(B, A, 1.0f / 27.0f);
    // avg z: ->(15,15,13)
    pool_line<225, 15, 225, 15, 195, 13, 13,   1,   1, false>(A, B, 1.0f);
    // avg y: ->(15,13,13)   lines (i,k)
    pool_line<195, 13, 195,  1, 169,  1, 13,  13,  13, false>(B, A, 1.0f);
    // avg x: ->(13,13,13)   lines (j,k)
    pool_line<169, 13,  13,  1,  13,  1, 13, 169, 169, false>(A, B, 1.0f / 27.0f);
}

// Kernel 1: s1[n] = smooth(alpha1 + alpha0 * cost[n])
__global__ void __launch_bounds__(256)
k_stage1(const float* __restrict__ cost, const float* __restrict__ alpha) {
    extern __shared__ float sm[];
    float* A = sm;           // PVOL floats
    float* B = sm + PVOL;    // BUFB floats (also 13^3 staging)
    int n = blockIdx.x;
    float a0 = alpha[0], a1 = alpha[1];
    const float* src = cost + (size_t)n * VOL;
    for (int v = threadIdx.x; v < VOL; v += blockDim.x)
        B[v] = a1 + a0 * src[v];
    __syncthreads();
    pad_edge(B, A);
    smooth_smem(A, B);
    float* dst = g_s1 + (size_t)n * VOL;
    for (int v = threadIdx.x; v < VOL; v += blockDim.x)
        dst[v] = B[v];
}

// Kernel 2: gather s1 over knn -> combine with original cost -> smooth -> s2
__global__ void __launch_bounds__(256)
k_stage2(const float* __restrict__ cost, const int* __restrict__ knn,
         const float* __restrict__ dist, const float* __restrict__ alpha) {
    extern __shared__ float sm[];
    float* A = sm;
    float* B = sm + PVOL;
    __shared__ float ws[KNB];
    __shared__ int   nb[KNB];
    int n = blockIdx.x;
    if (threadIdx.x < KNB) {
        ws[threadIdx.x] = __expf(-dist[n * KNB + threadIdx.x] * 0.005f); // 1/(2*SIGMA^2)
        nb[threadIdx.x] = knn[n * KNB + threadIdx.x];
    }
    __syncthreads();
    float w0 = ws[0], w1 = ws[1], w2 = ws[2], w3 = ws[3];
    float w4 = ws[4], w5 = ws[5], w6 = ws[6], w7 = ws[7];
    float inv_norm = 1.0f / (w0 + w1 + w2 + w3 + w4 + w5 + w6 + w7);
    const float* p0 = g_s1 + (size_t)nb[0] * VOL;
    const float* p1 = g_s1 + (size_t)nb[1] * VOL;
    const float* p2 = g_s1 + (size_t)nb[2] * VOL;
    const float* p3 = g_s1 + (size_t)nb[3] * VOL;
    const float* p4 = g_s1 + (size_t)nb[4] * VOL;
    const float* p5 = g_s1 + (size_t)nb[5] * VOL;
    const float* p6 = g_s1 + (size_t)nb[6] * VOL;
    const float* p7 = g_s1 + (size_t)nb[7] * VOL;
    float a0 = alpha[0], a1 = alpha[1], a2 = alpha[2], a3 = alpha[3], a4 = alpha[4];
    const float* src = cost + (size_t)n * VOL;
    for (int v = threadIdx.x; v < VOL; v += blockDim.x) {
        float g = w0 * p0[v] + w1 * p1[v] + w2 * p2[v] + w3 * p3[v]
                + w4 * p4[v] + w5 * p5[v] + w6 * p6[v] + w7 * p7[v];
        B[v] = a4 + a2 * (a1 + a0 * src[v]) + a3 * g * inv_norm;
    }
    __syncthreads();
    pad_edge(B, A);
    smooth_smem(A, B);
    float* dst = g_s2 + (size_t)n * VOL;
    for (int v = threadIdx.x; v < VOL; v += blockDim.x)
        dst[v] = B[v];
}

// Kernel 3: out[n] = alpha5 * (gather s2 over knn) / norm
__global__ void __launch_bounds__(256)
k_stage3(const int* __restrict__ knn, const float* __restrict__ dist,
         const float* __restrict__ alpha, float* __restrict__ out) {
    __shared__ float ws[KNB];
    __shared__ int   nb[KNB];
    int n = blockIdx.x;
    if (threadIdx.x < KNB) {
        ws[threadIdx.x] = __expf(-dist[n * KNB + threadIdx.x] * 0.005f);
        nb[threadIdx.x] = knn[n * KNB + threadIdx.x];
    }
    __syncthreads();
    float w0 = ws[0], w1 = ws[1], w2 = ws[2], w3 = ws[3];
    float w4 = ws[4], w5 = ws[5], w6 = ws[6], w7 = ws[7];
    float inv_norm = 1.0f / (w0 + w1 + w2 + w3 + w4 + w5 + w6 + w7);
    float s = alpha[5] * inv_norm;
    const float* p0 = g_s2 + (size_t)nb[0] * VOL;
    const float* p1 = g_s2 + (size_t)nb[1] * VOL;
    const float* p2 = g_s2 + (size_t)nb[2] * VOL;
    const float* p3 = g_s2 + (size_t)nb[3] * VOL;
    const float* p4 = g_s2 + (size_t)nb[4] * VOL;
    const float* p5 = g_s2 + (size_t)nb[5] * VOL;
    const float* p6 = g_s2 + (size_t)nb[6] * VOL;
    const float* p7 = g_s2 + (size_t)nb[7] * VOL;
    float* dst = out + (size_t)n * VOL;
    for (int v = threadIdx.x; v < VOL; v += blockDim.x) {
        float g = w0 * p0[v] + w1 * p1[v] + w2 * p2[v] + w3 * p3[v]
                + w4 * p4[v] + w5 * p5[v] + w6 * p6[v] + w7 * p7[v];
        dst[v] = s * g;
    }
}

extern "C" void kernel_launch(void* const* d_in, const int* in_sizes, int n_in,
                              void* d_out, int out_size) {
    const float* cost  = (const float*)d_in[0];
    const int*   knn   = (const int*)d_in[1];
    const float* dist  = (const float*)d_in[2];
    const float* alpha = (const float*)d_in[3];
    float* out = (float*)d_out;

    const int smem = (PVOL + BUFB) * (int)sizeof(float);  // 51984 B
    cudaFuncSetAttribute(k_stage1, cudaFuncAttributeMaxDynamicSharedMemorySize, smem);
    cudaFuncSetAttribute(k_stage2, cudaFuncAttributeMaxDynamicSharedMemorySize, smem);

    k_stage1<<<NN, 256, smem>>>(cost, alpha);
    k_stage2<<<NN, 256, smem>>>(cost, knn, dist, alpha);
    k_stage3<<<NN, 256>>>(knn, dist, alpha, out);
}